// round 1
// baseline (speedup 1.0000x reference)
#include <cuda_runtime.h>
#include <math.h>

#define B_    8
#define T_    1024
#define DIM_  2048
#define H_    16
#define NKV_  4
#define HD_   128
#define G_    4
#define KVD_  512          // NKV*HD
#define SCALE_ 0.08838834764831845f   // 128^-0.5
#define EPS_  1e-6f

// ---------------- scratch (static device globals: allocation-free) -------------
__device__ float g_q[B_*T_*DIM_];   // 64MB  q after gemm / norm+rope
__device__ float g_k[B_*T_*KVD_];   // 16MB
__device__ float g_v[B_*T_*KVD_];   // 16MB
__device__ float g_y[B_*T_*DIM_];   // 64MB  attention out, v-reject in place

// ---------------- GEMM: C[M,N] = A[M,K] * B[N,K]^T (both row-major) -----------
#define BM 128
#define BN 128
#define BK 16
__global__ __launch_bounds__(256) void gemm_abt(
    const float* __restrict__ A, const float* __restrict__ Bm,
    float* __restrict__ C, int M, int N, int K) {
  __shared__ float As[BK][BM];
  __shared__ float Bs[BK][BN];
  const int tid = threadIdx.x;
  const int bm = blockIdx.y * BM;
  const int bn = blockIdx.x * BN;
  const int tx = tid & 15, ty = tid >> 4;
  float acc[8][8];
#pragma unroll
  for (int i = 0; i < 8; i++)
#pragma unroll
    for (int j = 0; j < 8; j++) acc[i][j] = 0.f;

  for (int k0 = 0; k0 < K; k0 += BK) {
#pragma unroll
    for (int i = 0; i < 2; i++) {          // 128 rows x 16 cols of A
      int idx = tid + i * 256;
      int r = idx >> 2, c4 = (idx & 3) << 2;
      float4 va = *(const float4*)(A + (size_t)(bm + r) * K + k0 + c4);
      As[c4 + 0][r] = va.x; As[c4 + 1][r] = va.y;
      As[c4 + 2][r] = va.z; As[c4 + 3][r] = va.w;
    }
#pragma unroll
    for (int i = 0; i < 2; i++) {          // 128 rows x 16 cols of B
      int idx = tid + i * 256;
      int r = idx >> 2, c4 = (idx & 3) << 2;
      float4 vb = *(const float4*)(Bm + (size_t)(bn + r) * K + k0 + c4);
      Bs[c4 + 0][r] = vb.x; Bs[c4 + 1][r] = vb.y;
      Bs[c4 + 2][r] = vb.z; Bs[c4 + 3][r] = vb.w;
    }
    __syncthreads();
#pragma unroll
    for (int kk = 0; kk < BK; kk++) {
      float a[8], b[8];
      *(float4*)a       = *(const float4*)&As[kk][ty * 8];
      *(float4*)(a + 4) = *(const float4*)&As[kk][ty * 8 + 4];
      *(float4*)b       = *(const float4*)&Bs[kk][tx * 8];
      *(float4*)(b + 4) = *(const float4*)&Bs[kk][tx * 8 + 4];
#pragma unroll
      for (int i = 0; i < 8; i++)
#pragma unroll
        for (int j = 0; j < 8; j++) acc[i][j] += a[i] * b[j];
    }
    __syncthreads();
  }
#pragma unroll
  for (int i = 0; i < 8; i++) {
    float* crow = C + (size_t)(bm + ty * 8 + i) * N + bn + tx * 8;
    *(float4*)crow       = make_float4(acc[i][0], acc[i][1], acc[i][2], acc[i][3]);
    *(float4*)(crow + 4) = make_float4(acc[i][4], acc[i][5], acc[i][6], acc[i][7]);
  }
}

// ---------------- RMSNorm + RoPE (+gain), warp per head-row -------------------
__global__ void rms_rope_kernel(float* __restrict__ X, const float* __restrict__ gain,
                                int nheads, int nrows) {
  int gw = (int)((blockIdx.x * blockDim.x + threadIdx.x) >> 5);
  int lane = threadIdx.x & 31;
  if (gw >= nrows) return;
  int h = gw % nheads;
  int bt = gw / nheads;
  int t = bt % T_;
  float* row = X + (size_t)bt * (nheads * HD_) + h * HD_;
  int j0 = lane * 2;
  float x1a = row[j0],      x1b = row[j0 + 1];
  float x2a = row[64 + j0], x2b = row[64 + j0 + 1];
  float ss = x1a * x1a + x1b * x1b + x2a * x2a + x2b * x2b;
#pragma unroll
  for (int o = 16; o > 0; o >>= 1) ss += __shfl_xor_sync(0xffffffffu, ss, o);
  float rn = rsqrtf(ss * (1.f / HD_) + EPS_);
  float gm = (gain != nullptr) ? gain[h] * rn : rn;
  x1a *= gm; x1b *= gm; x2a *= gm; x2b *= gm;
  // RoPE tables (double for accuracy; freq index j maps to exponent j/64)
  const double lg = 9.210340371976184;  // log(10000)
  float inv0 = (float)exp(-(double)j0 / 64.0 * lg);
  float inv1 = (float)exp(-(double)(j0 + 1) / 64.0 * lg);
  float f0 = (float)t * inv0;
  float f1 = (float)t * inv1;
  double s0d, c0d, s1d, c1d;
  sincos((double)f0, &s0d, &c0d);
  sincos((double)f1, &s1d, &c1d);
  float c0 = (float)c0d, s0 = (float)s0d, c1 = (float)c1d, s1 = (float)s1d;
  row[j0]          = x1a * c0 - x2a * s0;
  row[j0 + 1]      = x1b * c1 - x2b * s1;
  row[64 + j0]     = x2a * c0 + x1a * s0;
  row[64 + j0 + 1] = x2b * c1 + x1b * s1;
}

// ---------------- Flash attention: 1 query row per thread --------------------
#define BQ  128
#define BKT 32
#define SMEM_FLASH ((128*129 + 2*32*128) * 4)

__global__ __launch_bounds__(128, 1) void flash_kernel(
    const float* __restrict__ Q, const float* __restrict__ K,
    const float* __restrict__ V, float* __restrict__ Y) {
  extern __shared__ float sm[];
  float* Qs = sm;               // transposed: Qs[d*129 + r]
  float* Ks = sm + 128 * 129;   // [32][128]
  float* Vs = Ks + 32 * 128;    // [32][128]
  const int tid = threadIdx.x;
  const int qtile = blockIdx.x;
  const int bh = blockIdx.y;
  const int b = bh >> 4;        // / H
  const int h = bh & 15;
  const int kv = h >> 2;        // / G
  const int q0 = qtile * BQ;
  const size_t qoff = ((size_t)b * T_ + q0) * DIM_ + h * HD_;

  // load Q tile transposed (coalesced gmem, conflict-free smem)
  for (int r = 0; r < BQ; r++)
    Qs[tid * 129 + r] = Q[qoff + (size_t)r * DIM_ + tid];
  __syncthreads();

  float acc[128];
#pragma unroll
  for (int d = 0; d < 128; d++) acc[d] = 0.f;
  float m = -INFINITY, l = 0.f;
  const int qi = q0 + tid;
  const int ntiles = (q0 + BQ) / BKT;
  const size_t kbase = (size_t)b * T_ * KVD_ + kv * HD_;

  for (int kt = 0; kt < ntiles; kt++) {
    const int s0 = kt * BKT;
#pragma unroll
    for (int i = 0; i < 8; i++) {           // 32x128 K & V tiles
      int f = i * 512 + tid * 4;
      int r = f >> 7, d = f & 127;
      *(float4*)&Ks[r * 128 + d] = *(const float4*)(K + kbase + (size_t)(s0 + r) * KVD_ + d);
      *(float4*)&Vs[r * 128 + d] = *(const float4*)(V + kbase + (size_t)(s0 + r) * KVD_ + d);
    }
    __syncthreads();

    float sreg[32];
#pragma unroll
    for (int s = 0; s < 32; s++) sreg[s] = 0.f;
#pragma unroll
    for (int d0 = 0; d0 < 128; d0 += 16) {
      float qf[16];
#pragma unroll
      for (int i = 0; i < 16; i++) qf[i] = Qs[(d0 + i) * 129 + tid];
#pragma unroll
      for (int s = 0; s < 32; s++) {
        float dot = sreg[s];
#pragma unroll
        for (int i = 0; i < 16; i++) dot += qf[i] * Ks[s * 128 + d0 + i];
        sreg[s] = dot;
      }
    }
    // causal mask + scale + running max
    float mt = m;
#pragma unroll
    for (int s = 0; s < 32; s++) {
      float v = (s0 + s <= qi) ? sreg[s] * SCALE_ : -INFINITY;
      sreg[s] = v;
      mt = fmaxf(mt, v);
    }
    float alpha = expf(m - mt);   // m=-inf first tile -> 0
    l *= alpha;
#pragma unroll
    for (int d = 0; d < 128; d++) acc[d] *= alpha;
#pragma unroll
    for (int s = 0; s < 32; s++) {
      float p = expf(sreg[s] - mt);
      l += p;
#pragma unroll
      for (int d = 0; d < 128; d++) acc[d] += p * Vs[s * 128 + d];
    }
    m = mt;
    __syncthreads();
  }

  // write out (transpose through smem for coalescing)
  __syncthreads();
  float linv = 1.f / l;
#pragma unroll
  for (int d = 0; d < 128; d++) Qs[d * 129 + tid] = acc[d] * linv;
  __syncthreads();
  for (int r = 0; r < BQ; r++)
    Y[qoff + (size_t)r * DIM_ + tid] = Qs[tid * 129 + r];
}

// ---------------- v-direction rejection: block per (b,t,kv) ------------------
__global__ __launch_bounds__(128) void vproj_kernel(const float* __restrict__ V,
                                                    float* __restrict__ Y) {
  const int btk = blockIdx.x;
  const int bt = btk >> 2, kv = btk & 3;
  const int d = threadIdx.x;
  const int lane = d & 31, wid = d >> 5;
  __shared__ float red[4];
  __shared__ float bcast;
  float vv = V[(size_t)bt * KVD_ + kv * HD_ + d];
  float ss = vv * vv;
#pragma unroll
  for (int o = 16; o > 0; o >>= 1) ss += __shfl_xor_sync(0xffffffffu, ss, o);
  if (lane == 0) red[wid] = ss;
  __syncthreads();
  if (d == 0) bcast = 1.f / (sqrtf(red[0] + red[1] + red[2] + red[3]) + 1e-8f);
  __syncthreads();
  float vn = vv * bcast;
#pragma unroll
  for (int g = 0; g < 4; g++) {
    size_t yi = (size_t)bt * DIM_ + (kv * 4 + g) * HD_ + d;
    float yv = Y[yi];
    float p = yv * vn;
#pragma unroll
    for (int o = 16; o > 0; o >>= 1) p += __shfl_xor_sync(0xffffffffu, p, o);
    __syncthreads();                 // previous red reads done
    if (lane == 0) red[wid] = p;
    __syncthreads();
    float dot = red[0] + red[1] + red[2] + red[3];
    Y[yi] = yv - dot * vn;
  }
}

// ---------------- launch ------------------------------------------------------
extern "C" void kernel_launch(void* const* d_in, const int* in_sizes, int n_in,
                              void* d_out, int out_size) {
  const float* x     = (const float*)d_in[0];
  const float* Wq    = (const float*)d_in[1];
  const float* Wk    = (const float*)d_in[2];
  const float* Wv    = (const float*)d_in[3];
  const float* Wproj = (const float*)d_in[4];
  const float* qgain = (const float*)d_in[5];
  float* out = (float*)d_out;

  float *qb, *kb, *vb, *yb;
  cudaGetSymbolAddress((void**)&qb, g_q);
  cudaGetSymbolAddress((void**)&kb, g_k);
  cudaGetSymbolAddress((void**)&vb, g_v);
  cudaGetSymbolAddress((void**)&yb, g_y);

  cudaFuncSetAttribute(flash_kernel, cudaFuncAttributeMaxDynamicSharedMemorySize,
                       SMEM_FLASH);

  const int M = B_ * T_;                      // 8192
  dim3 gbig(DIM_ / BN, M / BM);               // (16, 64)
  dim3 gkv(KVD_ / BN, M / BM);                // (4, 64)

  gemm_abt<<<gbig, 256>>>(x, Wq, qb, M, DIM_, DIM_);
  gemm_abt<<<gkv, 256>>>(x, Wk, kb, M, KVD_, DIM_);
  gemm_abt<<<gkv, 256>>>(x, Wv, vb, M, KVD_, DIM_);

  int qrows = M * H_;                         // 131072 warp-rows
  int krows = M * NKV_;                       // 32768
  rms_rope_kernel<<<(qrows * 32 + 255) / 256, 256>>>(qb, qgain, H_, qrows);
  rms_rope_kernel<<<(krows * 32 + 255) / 256, 256>>>(kb, nullptr, NKV_, krows);

  dim3 gf(T_ / BQ, B_ * H_);                  // (8, 128)
  flash_kernel<<<gf, 128, SMEM_FLASH>>>(qb, kb, vb, yb);

  vproj_kernel<<<M * NKV_, 128>>>(vb, yb);

  gemm_abt<<<gbig, 256>>>(yb, Wproj, out, M, DIM_, DIM_);
}

// round 2
// speedup vs baseline: 1.0718x; 1.0718x over previous
#include <cuda_runtime.h>
#include <math.h>

#define B_    8
#define T_    1024
#define DIM_  2048
#define H_    16
#define NKV_  4
#define HD_   128
#define KVD_  512
#define SCALE_ 0.08838834764831845f
#define EPS_  1e-6f

// ---------------- scratch ------------------------------------------------------
__device__ float g_q[B_*T_*DIM_];
__device__ float g_k[B_*T_*KVD_];
__device__ float g_v[B_*T_*KVD_];
__device__ float g_y[B_*T_*DIM_];
__device__ float g_rope[T_*64*2];   // {cos,sin} pairs per (t, freq)

// ---------------- RoPE table precompute (fp64, tiny) --------------------------
__global__ void rope_table_kernel() {
  int idx = blockIdx.x * blockDim.x + threadIdx.x;   // t*64 + j
  if (idx >= T_ * 64) return;
  int t = idx >> 6, j = idx & 63;
  const double lg = 9.210340371976184;               // log(10000)
  float inv = (float)exp(-(double)j / 64.0 * lg);    // match fp32 table build
  float f = (float)t * inv;
  double s, c;
  sincos((double)f, &s, &c);
  g_rope[idx * 2]     = (float)c;
  g_rope[idx * 2 + 1] = (float)s;
}

// ---------------- GEMM: C[M,N] = A[M,K]*B[N,K]^T, double-buffered -------------
#define BM 128
#define BN 128
#define BK 16
__global__ __launch_bounds__(256, 2) void gemm_abt(
    const float* __restrict__ A, const float* __restrict__ Bm,
    float* __restrict__ C, int M, int N, int K) {
  __shared__ float As[2][BK][BM];
  __shared__ float Bs[2][BK][BN];
  const int tid = threadIdx.x;
  const int bm = blockIdx.y * BM;
  const int bn = blockIdx.x * BN;
  const int tx = tid & 15, ty = tid >> 4;
  const int r0a = tid >> 2,        c0 = (tid & 3) << 2;   // load coords
  const int r1a = (tid + 256) >> 2;
  float acc[8][8];
#pragma unroll
  for (int i = 0; i < 8; i++)
#pragma unroll
    for (int j = 0; j < 8; j++) acc[i][j] = 0.f;

  float4 ra0, ra1, rb0, rb1;
  const int NT = K / BK;

  // prologue: load tile 0
  ra0 = *(const float4*)(A + (size_t)(bm + r0a) * K + c0);
  ra1 = *(const float4*)(A + (size_t)(bm + r1a) * K + c0);
  rb0 = *(const float4*)(Bm + (size_t)(bn + r0a) * K + c0);
  rb1 = *(const float4*)(Bm + (size_t)(bn + r1a) * K + c0);
  As[0][c0+0][r0a]=ra0.x; As[0][c0+1][r0a]=ra0.y; As[0][c0+2][r0a]=ra0.z; As[0][c0+3][r0a]=ra0.w;
  As[0][c0+0][r1a]=ra1.x; As[0][c0+1][r1a]=ra1.y; As[0][c0+2][r1a]=ra1.z; As[0][c0+3][r1a]=ra1.w;
  Bs[0][c0+0][r0a]=rb0.x; Bs[0][c0+1][r0a]=rb0.y; Bs[0][c0+2][r0a]=rb0.z; Bs[0][c0+3][r0a]=rb0.w;
  Bs[0][c0+0][r1a]=rb1.x; Bs[0][c0+1][r1a]=rb1.y; Bs[0][c0+2][r1a]=rb1.z; Bs[0][c0+3][r1a]=rb1.w;
  __syncthreads();

  for (int tile = 0; tile < NT; tile++) {
    const int buf = tile & 1;
    if (tile + 1 < NT) {
      const int k0 = (tile + 1) * BK;
      ra0 = *(const float4*)(A + (size_t)(bm + r0a) * K + k0 + c0);
      ra1 = *(const float4*)(A + (size_t)(bm + r1a) * K + k0 + c0);
      rb0 = *(const float4*)(Bm + (size_t)(bn + r0a) * K + k0 + c0);
      rb1 = *(const float4*)(Bm + (size_t)(bn + r1a) * K + k0 + c0);
    }
#pragma unroll
    for (int kk = 0; kk < BK; kk++) {
      float a[8], b[8];
      *(float4*)a       = *(const float4*)&As[buf][kk][ty * 8];
      *(float4*)(a + 4) = *(const float4*)&As[buf][kk][ty * 8 + 4];
      *(float4*)b       = *(const float4*)&Bs[buf][kk][tx * 8];
      *(float4*)(b + 4) = *(const float4*)&Bs[buf][kk][tx * 8 + 4];
#pragma unroll
      for (int i = 0; i < 8; i++)
#pragma unroll
        for (int j = 0; j < 8; j++) acc[i][j] += a[i] * b[j];
    }
    if (tile + 1 < NT) {
      const int nb = buf ^ 1;
      As[nb][c0+0][r0a]=ra0.x; As[nb][c0+1][r0a]=ra0.y; As[nb][c0+2][r0a]=ra0.z; As[nb][c0+3][r0a]=ra0.w;
      As[nb][c0+0][r1a]=ra1.x; As[nb][c0+1][r1a]=ra1.y; As[nb][c0+2][r1a]=ra1.z; As[nb][c0+3][r1a]=ra1.w;
      Bs[nb][c0+0][r0a]=rb0.x; Bs[nb][c0+1][r0a]=rb0.y; Bs[nb][c0+2][r0a]=rb0.z; Bs[nb][c0+3][r0a]=rb0.w;
      Bs[nb][c0+0][r1a]=rb1.x; Bs[nb][c0+1][r1a]=rb1.y; Bs[nb][c0+2][r1a]=rb1.z; Bs[nb][c0+3][r1a]=rb1.w;
      __syncthreads();
    }
  }
#pragma unroll
  for (int i = 0; i < 8; i++) {
    float* crow = C + (size_t)(bm + ty * 8 + i) * N + bn + tx * 8;
    *(float4*)crow       = make_float4(acc[i][0], acc[i][1], acc[i][2], acc[i][3]);
    *(float4*)(crow + 4) = make_float4(acc[i][4], acc[i][5], acc[i][6], acc[i][7]);
  }
}

// ---------------- RMSNorm + RoPE (+gain), warp per head-row, table lookup -----
__global__ void rms_rope_kernel(float* __restrict__ X, const float* __restrict__ gain,
                                int nheads, int nrows) {
  int gw = (int)((blockIdx.x * blockDim.x + threadIdx.x) >> 5);
  int lane = threadIdx.x & 31;
  if (gw >= nrows) return;
  int h = gw % nheads;
  int bt = gw / nheads;
  int t = bt % T_;
  float* row = X + (size_t)bt * (nheads * HD_) + h * HD_;
  float2 x1 = *(float2*)(row + lane * 2);
  float2 x2 = *(float2*)(row + 64 + lane * 2);
  float ss = x1.x*x1.x + x1.y*x1.y + x2.x*x2.x + x2.y*x2.y;
#pragma unroll
  for (int o = 16; o > 0; o >>= 1) ss += __shfl_xor_sync(0xffffffffu, ss, o);
  float rn = rsqrtf(ss * (1.f / HD_) + EPS_);
  float gm = (gain != nullptr) ? gain[h] * rn : rn;
  x1.x *= gm; x1.y *= gm; x2.x *= gm; x2.y *= gm;
  float4 cs = *(const float4*)(g_rope + (size_t)t * 128 + lane * 4); // c0,s0,c1,s1
  float2 o1, o2;
  o1.x = x1.x * cs.x - x2.x * cs.y;
  o1.y = x1.y * cs.z - x2.y * cs.w;
  o2.x = x2.x * cs.x + x1.x * cs.y;
  o2.y = x2.y * cs.z + x1.y * cs.w;
  *(float2*)(row + lane * 2)      = o1;
  *(float2*)(row + 64 + lane * 2) = o2;
}

// ---------------- Flash attention: 256 threads, 1 query row per thread --------
#define BQ  256
#define BKT 32
#define QS_STRIDE 257
#define SMEM_FLASH ((128*QS_STRIDE + 2*BKT*128) * 4)

__global__ __launch_bounds__(256, 1) void flash_kernel(
    const float* __restrict__ Q, const float* __restrict__ K,
    const float* __restrict__ V, float* __restrict__ Y) {
  extern __shared__ float sm[];
  float* Qs = sm;                          // transposed: Qs[d*257 + r]
  float* Ks = sm + 128 * QS_STRIDE;        // [32][128]
  float* Vs = Ks + BKT * 128;
  const int tid = threadIdx.x;
  const int qtile = gridDim.x - 1 - blockIdx.x;   // heavy tiles first
  const int bh = blockIdx.y;
  const int b = bh >> 4;
  const int h = bh & 15;
  const int kv = h >> 2;
  const int q0 = qtile * BQ;
  const size_t qoff = ((size_t)b * T_ + q0) * DIM_ + h * HD_;

  // load Q tile transposed
  for (int i = tid; i < BQ * 128; i += 256) {
    int r = i >> 7, d = i & 127;
    Qs[d * QS_STRIDE + r] = Q[qoff + (size_t)r * DIM_ + d];
  }
  __syncthreads();

  float acc[128];
#pragma unroll
  for (int d = 0; d < 128; d++) acc[d] = 0.f;
  float m = -INFINITY, l = 0.f;
  const int qi = q0 + tid;
  const int ntiles = (q0 + BQ) / BKT;
  const size_t kbase = (size_t)b * T_ * KVD_ + kv * HD_;

  for (int kt = 0; kt < ntiles; kt++) {
    const int s0 = kt * BKT;
#pragma unroll
    for (int i = 0; i < 4; i++) {          // 32x128 K & V tiles, float4
      int idx = i * 256 + tid;
      int r = idx >> 5, d4 = (idx & 31) << 2;
      *(float4*)&Ks[r * 128 + d4] = *(const float4*)(K + kbase + (size_t)(s0 + r) * KVD_ + d4);
      *(float4*)&Vs[r * 128 + d4] = *(const float4*)(V + kbase + (size_t)(s0 + r) * KVD_ + d4);
    }
    __syncthreads();

    float sreg[BKT];
#pragma unroll
    for (int s = 0; s < BKT; s++) sreg[s] = 0.f;
#pragma unroll
    for (int d0 = 0; d0 < 128; d0 += 16) {
      float qf[16];
#pragma unroll
      for (int i = 0; i < 16; i++) qf[i] = Qs[(d0 + i) * QS_STRIDE + tid];
#pragma unroll
      for (int s = 0; s < BKT; s++) {
        float dot = sreg[s];
#pragma unroll
        for (int i = 0; i < 16; i++) dot += qf[i] * Ks[s * 128 + d0 + i];
        sreg[s] = dot;
      }
    }
    float mt = m;
#pragma unroll
    for (int s = 0; s < BKT; s++) {
      float v = (s0 + s <= qi) ? sreg[s] * SCALE_ : -INFINITY;
      sreg[s] = v;
      mt = fmaxf(mt, v);
    }
    float alpha = expf(m - mt);
    l *= alpha;
#pragma unroll
    for (int d = 0; d < 128; d++) acc[d] *= alpha;
#pragma unroll
    for (int s = 0; s < BKT; s++) {
      float p = expf(sreg[s] - mt);
      l += p;
#pragma unroll
      for (int d = 0; d < 128; d++) acc[d] += p * Vs[s * 128 + d];
    }
    m = mt;
    __syncthreads();
  }

  // write out via transpose smem
  __syncthreads();
  float linv = 1.f / l;
#pragma unroll
  for (int d = 0; d < 128; d++) Qs[d * QS_STRIDE + tid] = acc[d] * linv;
  __syncthreads();
  for (int i = tid; i < BQ * 128; i += 256) {
    int r = i >> 7, d = i & 127;
    Y[qoff + (size_t)r * DIM_ + d] = Qs[d * QS_STRIDE + r];
  }
}

// ---------------- v-direction rejection: warp per (bt,kv), float4 -------------
__global__ __launch_bounds__(256) void vproj_kernel(const float* __restrict__ V,
                                                    float* __restrict__ Y) {
  const int gw = (blockIdx.x * blockDim.x + threadIdx.x) >> 5;
  const int lane = threadIdx.x & 31;
  if (gw >= B_ * T_ * NKV_) return;
  const int bt = gw >> 2, kv = gw & 3;
  float4 v4 = *(const float4*)(V + (size_t)bt * KVD_ + kv * HD_ + lane * 4);
  float ss = v4.x*v4.x + v4.y*v4.y + v4.z*v4.z + v4.w*v4.w;
#pragma unroll
  for (int o = 16; o > 0; o >>= 1) ss += __shfl_xor_sync(0xffffffffu, ss, o);
  float inv = 1.f / (sqrtf(ss) + 1e-8f);
  float4 vn = make_float4(v4.x*inv, v4.y*inv, v4.z*inv, v4.w*inv);
#pragma unroll
  for (int g = 0; g < 4; g++) {
    float* yp = Y + (size_t)bt * DIM_ + (kv * 4 + g) * HD_ + lane * 4;
    float4 y4 = *(float4*)yp;
    float p = y4.x*vn.x + y4.y*vn.y + y4.z*vn.z + y4.w*vn.w;
#pragma unroll
    for (int o = 16; o > 0; o >>= 1) p += __shfl_xor_sync(0xffffffffu, p, o);
    y4.x -= p * vn.x; y4.y -= p * vn.y; y4.z -= p * vn.z; y4.w -= p * vn.w;
    *(float4*)yp = y4;
  }
}

// ---------------- launch ------------------------------------------------------
extern "C" void kernel_launch(void* const* d_in, const int* in_sizes, int n_in,
                              void* d_out, int out_size) {
  const float* x     = (const float*)d_in[0];
  const float* Wq    = (const float*)d_in[1];
  const float* Wk    = (const float*)d_in[2];
  const float* Wv    = (const float*)d_in[3];
  const float* Wproj = (const float*)d_in[4];
  const float* qgain = (const float*)d_in[5];
  float* out = (float*)d_out;

  float *qb, *kb, *vb, *yb;
  cudaGetSymbolAddress((void**)&qb, g_q);
  cudaGetSymbolAddress((void**)&kb, g_k);
  cudaGetSymbolAddress((void**)&vb, g_v);
  cudaGetSymbolAddress((void**)&yb, g_y);

  cudaFuncSetAttribute(flash_kernel, cudaFuncAttributeMaxDynamicSharedMemorySize,
                       SMEM_FLASH);

  const int M = B_ * T_;
  dim3 gbig(DIM_ / BN, M / BM);
  dim3 gkv(KVD_ / BN, M / BM);

  rope_table_kernel<<<(T_ * 64 + 255) / 256, 256>>>();

  gemm_abt<<<gbig, 256>>>(x, Wq, qb, M, DIM_, DIM_);
  gemm_abt<<<gkv, 256>>>(x, Wk, kb, M, KVD_, DIM_);
  gemm_abt<<<gkv, 256>>>(x, Wv, vb, M, KVD_, DIM_);

  int qrows = M * H_;
  int krows = M * NKV_;
  rms_rope_kernel<<<(qrows * 32 + 255) / 256, 256>>>(qb, qgain, H_, qrows);
  rms_rope_kernel<<<(krows * 32 + 255) / 256, 256>>>(kb, nullptr, NKV_, krows);

  dim3 gf(T_ / BQ, B_ * H_);
  flash_kernel<<<gf, 256, SMEM_FLASH>>>(qb, kb, vb, yb);

  vproj_kernel<<<(M * NKV_ * 32 + 255) / 256, 256>>>(vb, yb);

  gemm_abt<<<gbig, 256>>>(yb, Wproj, out, M, DIM_, DIM_);
}

// round 4
// speedup vs baseline: 1.7848x; 1.6652x over previous
#include <cuda_runtime.h>
#include <cuda_bf16.h>
#include <math.h>
#include <cstdint>

#define B_    8
#define T_    1024
#define DIM_  2048
#define H_    16
#define NKV_  4
#define HD_   128
#define KVD_  512
#define SCALE_ 0.08838834764831845f
#define EPS_  1e-6f

// ---------------- scratch ------------------------------------------------------
__device__ float g_q[B_*T_*DIM_];
__device__ float g_k[B_*T_*KVD_];
__device__ float g_v[B_*T_*KVD_];
__device__ float g_y[B_*T_*DIM_];
__device__ float g_rope[T_*64*2];
// bf16 hi/lo planes (x planes reused for y later)
__device__ __nv_bfloat16 g_xh[B_*T_*DIM_];
__device__ __nv_bfloat16 g_xl[B_*T_*DIM_];
__device__ __nv_bfloat16 g_wqh[DIM_*DIM_];
__device__ __nv_bfloat16 g_wql[DIM_*DIM_];
__device__ __nv_bfloat16 g_wkh[KVD_*DIM_];
__device__ __nv_bfloat16 g_wkl[KVD_*DIM_];
__device__ __nv_bfloat16 g_wvh[KVD_*DIM_];
__device__ __nv_bfloat16 g_wvl[KVD_*DIM_];
__device__ __nv_bfloat16 g_wph[DIM_*DIM_];
__device__ __nv_bfloat16 g_wpl[DIM_*DIM_];

// ---------------- helpers ------------------------------------------------------
__device__ __forceinline__ uint32_t smem_u32(const void* p) {
  uint32_t a;
  asm("{ .reg .u64 t; cvta.to.shared.u64 t, %1; cvt.u32.u64 %0, t; }" : "=r"(a) : "l"(p));
  return a;
}
#define CP_ASYNC16(dst, src) \
  asm volatile("cp.async.cg.shared.global [%0], [%1], 16;" :: "r"(dst), "l"(src))
#define CP_COMMIT() asm volatile("cp.async.commit_group;" ::: "memory")
#define CP_WAIT1() asm volatile("cp.async.wait_group 1;" ::: "memory")
#define CP_WAIT0() asm volatile("cp.async.wait_group 0;" ::: "memory")

__device__ __forceinline__ void ldsm4(uint32_t* r, uint32_t addr) {
  asm volatile("ldmatrix.sync.aligned.m8n8.x4.shared.b16 {%0,%1,%2,%3}, [%4];"
               : "=r"(r[0]), "=r"(r[1]), "=r"(r[2]), "=r"(r[3]) : "r"(addr));
}
__device__ __forceinline__ void mma_bf16(float* d, const uint32_t* a, const uint32_t* b) {
  asm volatile("mma.sync.aligned.m16n8k16.row.col.f32.bf16.bf16.f32 "
               "{%0,%1,%2,%3}, {%4,%5,%6,%7}, {%8,%9}, {%0,%1,%2,%3};"
               : "+f"(d[0]), "+f"(d[1]), "+f"(d[2]), "+f"(d[3])
               : "r"(a[0]), "r"(a[1]), "r"(a[2]), "r"(a[3]), "r"(b[0]), "r"(b[1]));
}

// ---------------- RoPE table precompute (fp64, tiny) --------------------------
__global__ void rope_table_kernel() {
  int idx = blockIdx.x * blockDim.x + threadIdx.x;
  if (idx >= T_ * 64) return;
  int t = idx >> 6, j = idx & 63;
  const double lg = 9.210340371976184;
  float inv = (float)exp(-(double)j / 64.0 * lg);
  float f = (float)t * inv;
  double s, c;
  sincos((double)f, &s, &c);
  g_rope[idx * 2]     = (float)c;
  g_rope[idx * 2 + 1] = (float)s;
}

// ---------------- f32 -> bf16 hi/lo split --------------------------------------
__global__ __launch_bounds__(256) void split_kernel(const float* __restrict__ X,
                                                    __nv_bfloat16* __restrict__ Hh,
                                                    __nv_bfloat16* __restrict__ Ll, int n4) {
  int i = blockIdx.x * blockDim.x + threadIdx.x;
  if (i >= n4) return;
  float4 v = *(const float4*)(X + (size_t)i * 4);
  __nv_bfloat16 h0 = __float2bfloat16(v.x), h1 = __float2bfloat16(v.y);
  __nv_bfloat16 h2 = __float2bfloat16(v.z), h3 = __float2bfloat16(v.w);
  __nv_bfloat16 l0 = __float2bfloat16(v.x - __bfloat162float(h0));
  __nv_bfloat16 l1 = __float2bfloat16(v.y - __bfloat162float(h1));
  __nv_bfloat16 l2 = __float2bfloat16(v.z - __bfloat162float(h2));
  __nv_bfloat16 l3 = __float2bfloat16(v.w - __bfloat162float(h3));
  __nv_bfloat162 hp0{h0, h1}, hp1{h2, h3}, lp0{l0, l1}, lp1{l2, l3};
  *(uint2*)(Hh + (size_t)i * 4) = make_uint2(*(uint32_t*)&hp0, *(uint32_t*)&hp1);
  *(uint2*)(Ll + (size_t)i * 4) = make_uint2(*(uint32_t*)&lp0, *(uint32_t*)&lp1);
}

// ---------------- HMMA GEMM: C[M,N] = A[M,K]*B[N,K]^T, bf16 hi/lo split --------
// Block 128x128, 8 warps (warp tile 64x32), K-chunk 64, cp.async double buffer.
#define GT (128 * 64 * 2)               // 16KB per bf16 tile
#define SMEM_HG (2 * 4 * GT)            // 128KB

__global__ __launch_bounds__(256, 1) void gemm_hmma(
    const __nv_bfloat16* __restrict__ Ah, const __nv_bfloat16* __restrict__ Al,
    const __nv_bfloat16* __restrict__ Bh, const __nv_bfloat16* __restrict__ Bl,
    float* __restrict__ C, int N, int K) {
  extern __shared__ char sm[];
  const uint32_t sb = smem_u32(sm);
  const int tid = threadIdx.x;
  const int l = tid & 31, w = tid >> 5;
  const int bm = blockIdx.y * 128, bn = blockIdx.x * 128;
  const int wm = (w & 1) * 64, wn = (w >> 1) * 32;

  // per-thread load slots: 4 16B-chunks per tile (1024 chunks / 256 thr)
  int ldrow[4], ldkcol[4]; uint32_t lddst[4];
#pragma unroll
  for (int s = 0; s < 4; s++) {
    int ch = tid + s * 256;
    ldrow[s] = ch >> 3;
    ldkcol[s] = ch & 7;
    lddst[s] = (uint32_t)(ldrow[s] * 128 + ((ldkcol[s] * 16) ^ ((ldrow[s] & 7) << 4)));
  }

  // per-lane ldmatrix geometry
  const int arow = (l & 7) + ((l >> 3) & 1) * 8;
  const int akb  = (l >> 4) * 16;
  const int brow = (l & 7) + (l >> 4) * 8;
  const int bkb  = ((l >> 3) & 1) * 16;
  const int kxor = (l & 7) << 4;
  int aoff[4], boff[2];
#pragma unroll
  for (int i = 0; i < 4; i++) aoff[i] = (wm + i * 16 + arow) * 128;
#pragma unroll
  for (int j = 0; j < 2; j++) boff[j] = (wn + j * 16 + brow) * 128;

  float acc[4][4][4];
#pragma unroll
  for (int i = 0; i < 4; i++)
#pragma unroll
    for (int j = 0; j < 4; j++)
#pragma unroll
      for (int r = 0; r < 4; r++) acc[i][j][r] = 0.f;

  const int NC = K / 64;

  // chunk issue: tiles order Ah, Al, Bh, Bl
#define ISSUE_CHUNK(cc, buf) do {                                              \
    uint32_t base = sb + (buf) * 4 * GT;                                       \
    const __nv_bfloat16* srcs[4] = {Ah, Al, Bh, Bl};                           \
    _Pragma("unroll")                                                          \
    for (int tile = 0; tile < 4; tile++) {                                     \
      int rb = (tile < 2) ? bm : bn;                                           \
      const __nv_bfloat16* sp = srcs[tile];                                    \
      _Pragma("unroll")                                                        \
      for (int s = 0; s < 4; s++) {                                            \
        const __nv_bfloat16* src = sp + (size_t)(rb + ldrow[s]) * K +          \
                                   (cc) * 64 + ldkcol[s] * 8;                  \
        CP_ASYNC16(base + tile * GT + lddst[s], src);                          \
      }                                                                        \
    }                                                                          \
    CP_COMMIT();                                                               \
  } while (0)

  ISSUE_CHUNK(0, 0);

  for (int c = 0; c < NC; c++) {
    const int buf = c & 1;
    if (c + 1 < NC) { ISSUE_CHUNK(c + 1, buf ^ 1); CP_WAIT1(); }
    else            { CP_WAIT0(); }
    __syncthreads();

    const uint32_t tb = sb + buf * 4 * GT;
#pragma unroll
    for (int kc = 0; kc < 4; kc++) {
      uint32_t ah[4][4], al[4][4], bh[2][4], bl[2][4];
      const uint32_t kA = (uint32_t)((kc * 32 + akb) ^ kxor);
      const uint32_t kB = (uint32_t)((kc * 32 + bkb) ^ kxor);
#pragma unroll
      for (int i = 0; i < 4; i++) {
        ldsm4(ah[i], tb + aoff[i] + kA);
        ldsm4(al[i], tb + GT + aoff[i] + kA);
      }
#pragma unroll
      for (int j = 0; j < 2; j++) {
        ldsm4(bh[j], tb + 2 * GT + boff[j] + kB);
        ldsm4(bl[j], tb + 3 * GT + boff[j] + kB);
      }
#pragma unroll
      for (int i = 0; i < 4; i++)
#pragma unroll
        for (int jf = 0; jf < 4; jf++) {
          const uint32_t* bph = &bh[jf >> 1][(jf & 1) * 2];
          const uint32_t* bpl = &bl[jf >> 1][(jf & 1) * 2];
          mma_bf16(acc[i][jf], ah[i], bph);
          mma_bf16(acc[i][jf], ah[i], bpl);
          mma_bf16(acc[i][jf], al[i], bph);
        }
    }
    __syncthreads();
  }
#undef ISSUE_CHUNK

  // epilogue: direct float2 stores
  const int r0 = bm + wm + (l >> 2);
  const int c0 = bn + wn + (l & 3) * 2;
#pragma unroll
  for (int i = 0; i < 4; i++)
#pragma unroll
    for (int j = 0; j < 4; j++) {
      float* p0 = C + (size_t)(r0 + i * 16) * N + c0 + j * 8;
      float* p1 = C + (size_t)(r0 + i * 16 + 8) * N + c0 + j * 8;
      *(float2*)p0 = make_float2(acc[i][j][0], acc[i][j][1]);
      *(float2*)p1 = make_float2(acc[i][j][2], acc[i][j][3]);
    }
}

// ---------------- RMSNorm + RoPE (+gain) --------------------------------------
__global__ void rms_rope_kernel(float* __restrict__ X, const float* __restrict__ gain,
                                int nheads, int nrows) {
  int gw = (int)((blockIdx.x * blockDim.x + threadIdx.x) >> 5);
  int lane = threadIdx.x & 31;
  if (gw >= nrows) return;
  int h = gw % nheads;
  int bt = gw / nheads;
  int t = bt % T_;
  float* row = X + (size_t)bt * (nheads * HD_) + h * HD_;
  float2 x1 = *(float2*)(row + lane * 2);
  float2 x2 = *(float2*)(row + 64 + lane * 2);
  float ss = x1.x*x1.x + x1.y*x1.y + x2.x*x2.x + x2.y*x2.y;
#pragma unroll
  for (int o = 16; o > 0; o >>= 1) ss += __shfl_xor_sync(0xffffffffu, ss, o);
  float rn = rsqrtf(ss * (1.f / HD_) + EPS_);
  float gm = (gain != nullptr) ? gain[h] * rn : rn;
  x1.x *= gm; x1.y *= gm; x2.x *= gm; x2.y *= gm;
  float4 cs = *(const float4*)(g_rope + (size_t)t * 128 + lane * 4);
  float2 o1, o2;
  o1.x = x1.x * cs.x - x2.x * cs.y;
  o1.y = x1.y * cs.z - x2.y * cs.w;
  o2.x = x2.x * cs.x + x1.x * cs.y;
  o2.y = x2.y * cs.z + x1.y * cs.w;
  *(float2*)(row + lane * 2)      = o1;
  *(float2*)(row + 64 + lane * 2) = o2;
}

// ---------------- Flash attention ---------------------------------------------
#define BQ  256
#define BKT 32
#define QS_STRIDE 257
#define SMEM_FLASH ((128*QS_STRIDE + 2*BKT*128) * 4)

__global__ __launch_bounds__(256, 1) void flash_kernel(
    const float* __restrict__ Q, const float* __restrict__ K,
    const float* __restrict__ V, float* __restrict__ Y) {
  extern __shared__ float smf[];
  float* Qs = smf;
  float* Ks = smf + 128 * QS_STRIDE;
  float* Vs = Ks + BKT * 128;
  const int tid = threadIdx.x;
  const int qtile = gridDim.x - 1 - blockIdx.x;
  const int bh = blockIdx.y;
  const int b = bh >> 4;
  const int h = bh & 15;
  const int kv = h >> 2;
  const int q0 = qtile * BQ;
  const size_t qoff = ((size_t)b * T_ + q0) * DIM_ + h * HD_;

  for (int i = tid; i < BQ * 128; i += 256) {
    int r = i >> 7, d = i & 127;
    Qs[d * QS_STRIDE + r] = Q[qoff + (size_t)r * DIM_ + d];
  }
  __syncthreads();

  float acc[128];
#pragma unroll
  for (int d = 0; d < 128; d++) acc[d] = 0.f;
  float m = -INFINITY, l = 0.f;
  const int qi = q0 + tid;
  const int ntiles = (q0 + BQ) / BKT;
  const size_t kbase = (size_t)b * T_ * KVD_ + kv * HD_;

  for (int kt = 0; kt < ntiles; kt++) {
    const int s0 = kt * BKT;
#pragma unroll
    for (int i = 0; i < 4; i++) {
      int idx = i * 256 + tid;
      int r = idx >> 5, d4 = (idx & 31) << 2;
      *(float4*)&Ks[r * 128 + d4] = *(const float4*)(K + kbase + (size_t)(s0 + r) * KVD_ + d4);
      *(float4*)&Vs[r * 128 + d4] = *(const float4*)(V + kbase + (size_t)(s0 + r) * KVD_ + d4);
    }
    __syncthreads();

    float sreg[BKT];
#pragma unroll
    for (int s = 0; s < BKT; s++) sreg[s] = 0.f;
#pragma unroll
    for (int d0 = 0; d0 < 128; d0 += 16) {
      float qf[16];
#pragma unroll
      for (int i = 0; i < 16; i++) qf[i] = Qs[(d0 + i) * QS_STRIDE + tid];
#pragma unroll
      for (int s = 0; s < BKT; s++) {
        float dot = sreg[s];
#pragma unroll
        for (int i = 0; i < 16; i++) dot += qf[i] * Ks[s * 128 + d0 + i];
        sreg[s] = dot;
      }
    }
    float mt = m;
#pragma unroll
    for (int s = 0; s < BKT; s++) {
      float v = (s0 + s <= qi) ? sreg[s] * SCALE_ : -INFINITY;
      sreg[s] = v;
      mt = fmaxf(mt, v);
    }
    float alpha = expf(m - mt);
    l *= alpha;
#pragma unroll
    for (int d = 0; d < 128; d++) acc[d] *= alpha;
#pragma unroll
    for (int s = 0; s < BKT; s++) {
      float p = expf(sreg[s] - mt);
      l += p;
#pragma unroll
      for (int d = 0; d < 128; d++) acc[d] += p * Vs[s * 128 + d];
    }
    m = mt;
    __syncthreads();
  }

  __syncthreads();
  float linv = 1.f / l;
#pragma unroll
  for (int d = 0; d < 128; d++) Qs[d * QS_STRIDE + tid] = acc[d] * linv;
  __syncthreads();
  for (int i = tid; i < BQ * 128; i += 256) {
    int r = i >> 7, d = i & 127;
    Y[qoff + (size_t)r * DIM_ + d] = Qs[d * QS_STRIDE + r];
  }
}

// ---------------- v-direction rejection ----------------------------------------
__global__ __launch_bounds__(256) void vproj_kernel(const float* __restrict__ V,
                                                    float* __restrict__ Y) {
  const int gw = (blockIdx.x * blockDim.x + threadIdx.x) >> 5;
  const int lane = threadIdx.x & 31;
  if (gw >= B_ * T_ * NKV_) return;
  const int bt = gw >> 2, kv = gw & 3;
  float4 v4 = *(const float4*)(V + (size_t)bt * KVD_ + kv * HD_ + lane * 4);
  float ss = v4.x*v4.x + v4.y*v4.y + v4.z*v4.z + v4.w*v4.w;
#pragma unroll
  for (int o = 16; o > 0; o >>= 1) ss += __shfl_xor_sync(0xffffffffu, ss, o);
  float inv = 1.f / (sqrtf(ss) + 1e-8f);
  float4 vn = make_float4(v4.x*inv, v4.y*inv, v4.z*inv, v4.w*inv);
#pragma unroll
  for (int g = 0; g < 4; g++) {
    float* yp = Y + (size_t)bt * DIM_ + (kv * 4 + g) * HD_ + lane * 4;
    float4 y4 = *(float4*)yp;
    float p = y4.x*vn.x + y4.y*vn.y + y4.z*vn.z + y4.w*vn.w;
#pragma unroll
    for (int o = 16; o > 0; o >>= 1) p += __shfl_xor_sync(0xffffffffu, p, o);
    y4.x -= p * vn.x; y4.y -= p * vn.y; y4.z -= p * vn.z; y4.w -= p * vn.w;
    *(float4*)yp = y4;
  }
}

// ---------------- launch ------------------------------------------------------
extern "C" void kernel_launch(void* const* d_in, const int* in_sizes, int n_in,
                              void* d_out, int out_size) {
  const float* x     = (const float*)d_in[0];
  const float* Wq    = (const float*)d_in[1];
  const float* Wk    = (const float*)d_in[2];
  const float* Wv    = (const float*)d_in[3];
  const float* Wproj = (const float*)d_in[4];
  const float* qgain = (const float*)d_in[5];
  float* out = (float*)d_out;

  float *qb, *kb, *vb, *yb;
  cudaGetSymbolAddress((void**)&qb, g_q);
  cudaGetSymbolAddress((void**)&kb, g_k);
  cudaGetSymbolAddress((void**)&vb, g_v);
  cudaGetSymbolAddress((void**)&yb, g_y);
  __nv_bfloat16 *xh, *xl, *wqh, *wql, *wkh, *wkl, *wvh, *wvl, *wph, *wpl;
  cudaGetSymbolAddress((void**)&xh, g_xh);
  cudaGetSymbolAddress((void**)&xl, g_xl);
  cudaGetSymbolAddress((void**)&wqh, g_wqh);
  cudaGetSymbolAddress((void**)&wql, g_wql);
  cudaGetSymbolAddress((void**)&wkh, g_wkh);
  cudaGetSymbolAddress((void**)&wkl, g_wkl);
  cudaGetSymbolAddress((void**)&wvh, g_wvh);
  cudaGetSymbolAddress((void**)&wvl, g_wvl);
  cudaGetSymbolAddress((void**)&wph, g_wph);
  cudaGetSymbolAddress((void**)&wpl, g_wpl);

  cudaFuncSetAttribute(gemm_hmma, cudaFuncAttributeMaxDynamicSharedMemorySize, SMEM_HG);
  cudaFuncSetAttribute(flash_kernel, cudaFuncAttributeMaxDynamicSharedMemorySize, SMEM_FLASH);

  const int M = B_ * T_;
  dim3 gbig(DIM_ / 128, M / 128);   // (16, 64)
  dim3 gkv(KVD_ / 128, M / 128);    // (4, 64)

  rope_table_kernel<<<(T_ * 64 + 255) / 256, 256>>>();

  // splits
  split_kernel<<<(M * DIM_ / 4 + 255) / 256, 256>>>(x, xh, xl, M * DIM_ / 4);
  split_kernel<<<(DIM_ * DIM_ / 4 + 255) / 256, 256>>>(Wq, wqh, wql, DIM_ * DIM_ / 4);
  split_kernel<<<(KVD_ * DIM_ / 4 + 255) / 256, 256>>>(Wk, wkh, wkl, KVD_ * DIM_ / 4);
  split_kernel<<<(KVD_ * DIM_ / 4 + 255) / 256, 256>>>(Wv, wvh, wvl, KVD_ * DIM_ / 4);
  split_kernel<<<(DIM_ * DIM_ / 4 + 255) / 256, 256>>>(Wproj, wph, wpl, DIM_ * DIM_ / 4);

  gemm_hmma<<<gbig, 256, SMEM_HG>>>(xh, xl, wqh, wql, qb, DIM_, DIM_);
  gemm_hmma<<<gkv, 256, SMEM_HG>>>(xh, xl, wkh, wkl, kb, KVD_, DIM_);
  gemm_hmma<<<gkv, 256, SMEM_HG>>>(xh, xl, wvh, wvl, vb, KVD_, DIM_);

  int qrows = M * H_;
  int krows = M * NKV_;
  rms_rope_kernel<<<(qrows * 32 + 255) / 256, 256>>>(qb, qgain, H_, qrows);
  rms_rope_kernel<<<(krows * 32 + 255) / 256, 256>>>(kb, nullptr, NKV_, krows);

  dim3 gf(T_ / BQ, B_ * H_);
  flash_kernel<<<gf, 256, SMEM_FLASH>>>(qb, kb, vb, yb);

  vproj_kernel<<<(M * NKV_ * 32 + 255) / 256, 256>>>(vb, yb);

  // reuse x planes for y
  split_kernel<<<(M * DIM_ / 4 + 255) / 256, 256>>>(yb, xh, xl, M * DIM_ / 4);
  gemm_hmma<<<gbig, 256, SMEM_HG>>>(xh, xl, wph, wpl, out, DIM_, DIM_);
}

// round 5
// speedup vs baseline: 4.7960x; 2.6871x over previous
#include <cuda_runtime.h>
#include <cuda_bf16.h>
#include <math.h>
#include <cstdint>

#define B_    8
#define T_    1024
#define DIM_  2048
#define H_    16
#define NKV_  4
#define HD_   128
#define KVD_  512
#define SCALE_ 0.08838834764831845f
#define EPS_  1e-6f

// ---------------- scratch ------------------------------------------------------
__device__ float g_q[B_*T_*DIM_];
__device__ float g_k[B_*T_*KVD_];
__device__ float g_v[B_*T_*KVD_];
__device__ float g_y[B_*T_*DIM_];
__device__ float g_rope[T_*64*2];
__device__ __nv_bfloat16 g_xh[B_*T_*DIM_];
__device__ __nv_bfloat16 g_xl[B_*T_*DIM_];
__device__ __nv_bfloat16 g_wqh[DIM_*DIM_];
__device__ __nv_bfloat16 g_wql[DIM_*DIM_];
__device__ __nv_bfloat16 g_wkh[KVD_*DIM_];
__device__ __nv_bfloat16 g_wkl[KVD_*DIM_];
__device__ __nv_bfloat16 g_wvh[KVD_*DIM_];
__device__ __nv_bfloat16 g_wvl[KVD_*DIM_];
__device__ __nv_bfloat16 g_wph[DIM_*DIM_];
__device__ __nv_bfloat16 g_wpl[DIM_*DIM_];
// attention operand planes
__device__ __nv_bfloat16 g_qh[B_*T_*DIM_];
__device__ __nv_bfloat16 g_ql[B_*T_*DIM_];
__device__ __nv_bfloat16 g_kh[B_*T_*KVD_];
__device__ __nv_bfloat16 g_kl[B_*T_*KVD_];
__device__ __nv_bfloat16 g_vth[B_*NKV_*HD_*T_];   // [b*4+kv][dim][t]
__device__ __nv_bfloat16 g_vtl[B_*NKV_*HD_*T_];

// ---------------- helpers ------------------------------------------------------
__device__ __forceinline__ uint32_t smem_u32(const void* p) {
  uint32_t a;
  asm("{ .reg .u64 t; cvta.to.shared.u64 t, %1; cvt.u32.u64 %0, t; }" : "=r"(a) : "l"(p));
  return a;
}
#define CP_ASYNC16(dst, src) \
  asm volatile("cp.async.cg.shared.global [%0], [%1], 16;" :: "r"(dst), "l"(src))
#define CP_COMMIT() asm volatile("cp.async.commit_group;" ::: "memory")
#define CP_WAIT1() asm volatile("cp.async.wait_group 1;" ::: "memory")
#define CP_WAIT0() asm volatile("cp.async.wait_group 0;" ::: "memory")

__device__ __forceinline__ void ldsm4(uint32_t* r, uint32_t addr) {
  asm volatile("ldmatrix.sync.aligned.m8n8.x4.shared.b16 {%0,%1,%2,%3}, [%4];"
               : "=r"(r[0]), "=r"(r[1]), "=r"(r[2]), "=r"(r[3]) : "r"(addr));
}
__device__ __forceinline__ void mma_bf16(float* d, const uint32_t* a, const uint32_t* b) {
  asm volatile("mma.sync.aligned.m16n8k16.row.col.f32.bf16.bf16.f32 "
               "{%0,%1,%2,%3}, {%4,%5,%6,%7}, {%8,%9}, {%0,%1,%2,%3};"
               : "+f"(d[0]), "+f"(d[1]), "+f"(d[2]), "+f"(d[3])
               : "r"(a[0]), "r"(a[1]), "r"(a[2]), "r"(a[3]), "r"(b[0]), "r"(b[1]));
}
__device__ __forceinline__ uint32_t pack_bf2(float a, float b) {
  __nv_bfloat162 p{__float2bfloat16(a), __float2bfloat16(b)};
  return *(uint32_t*)&p;
}

// ---------------- RoPE table precompute (fp64, tiny) --------------------------
__global__ void rope_table_kernel() {
  int idx = blockIdx.x * blockDim.x + threadIdx.x;
  if (idx >= T_ * 64) return;
  int t = idx >> 6, j = idx & 63;
  const double lg = 9.210340371976184;
  float inv = (float)exp(-(double)j / 64.0 * lg);
  float f = (float)t * inv;
  double s, c;
  sincos((double)f, &s, &c);
  g_rope[idx * 2]     = (float)c;
  g_rope[idx * 2 + 1] = (float)s;
}

// ---------------- f32 -> bf16 hi/lo split --------------------------------------
__global__ __launch_bounds__(256) void split_kernel(const float* __restrict__ X,
                                                    __nv_bfloat16* __restrict__ Hh,
                                                    __nv_bfloat16* __restrict__ Ll, int n4) {
  int i = blockIdx.x * blockDim.x + threadIdx.x;
  if (i >= n4) return;
  float4 v = *(const float4*)(X + (size_t)i * 4);
  __nv_bfloat16 h0 = __float2bfloat16(v.x), h1 = __float2bfloat16(v.y);
  __nv_bfloat16 h2 = __float2bfloat16(v.z), h3 = __float2bfloat16(v.w);
  __nv_bfloat16 l0 = __float2bfloat16(v.x - __bfloat162float(h0));
  __nv_bfloat16 l1 = __float2bfloat16(v.y - __bfloat162float(h1));
  __nv_bfloat16 l2 = __float2bfloat16(v.z - __bfloat162float(h2));
  __nv_bfloat16 l3 = __float2bfloat16(v.w - __bfloat162float(h3));
  __nv_bfloat162 hp0{h0, h1}, hp1{h2, h3}, lp0{l0, l1}, lp1{l2, l3};
  *(uint2*)(Hh + (size_t)i * 4) = make_uint2(*(uint32_t*)&hp0, *(uint32_t*)&hp1);
  *(uint2*)(Ll + (size_t)i * 4) = make_uint2(*(uint32_t*)&lp0, *(uint32_t*)&lp1);
}

// ---------------- HMMA GEMM (unchanged from round 4) ---------------------------
#define GT (128 * 64 * 2)
#define SMEM_HG (2 * 4 * GT)

__global__ __launch_bounds__(256, 1) void gemm_hmma(
    const __nv_bfloat16* __restrict__ Ah, const __nv_bfloat16* __restrict__ Al,
    const __nv_bfloat16* __restrict__ Bh, const __nv_bfloat16* __restrict__ Bl,
    float* __restrict__ C, int N, int K) {
  extern __shared__ char sm[];
  const uint32_t sb = smem_u32(sm);
  const int tid = threadIdx.x;
  const int l = tid & 31, w = tid >> 5;
  const int bm = blockIdx.y * 128, bn = blockIdx.x * 128;
  const int wm = (w & 1) * 64, wn = (w >> 1) * 32;

  int ldrow[4], ldkcol[4]; uint32_t lddst[4];
#pragma unroll
  for (int s = 0; s < 4; s++) {
    int ch = tid + s * 256;
    ldrow[s] = ch >> 3;
    ldkcol[s] = ch & 7;
    lddst[s] = (uint32_t)(ldrow[s] * 128 + ((ldkcol[s] * 16) ^ ((ldrow[s] & 7) << 4)));
  }
  const int arow = (l & 7) + ((l >> 3) & 1) * 8;
  const int akb  = (l >> 4) * 16;
  const int brow = (l & 7) + (l >> 4) * 8;
  const int bkb  = ((l >> 3) & 1) * 16;
  const int kxor = (l & 7) << 4;
  int aoff[4], boff[2];
#pragma unroll
  for (int i = 0; i < 4; i++) aoff[i] = (wm + i * 16 + arow) * 128;
#pragma unroll
  for (int j = 0; j < 2; j++) boff[j] = (wn + j * 16 + brow) * 128;

  float acc[4][4][4];
#pragma unroll
  for (int i = 0; i < 4; i++)
#pragma unroll
    for (int j = 0; j < 4; j++)
#pragma unroll
      for (int r = 0; r < 4; r++) acc[i][j][r] = 0.f;

  const int NC = K / 64;

#define ISSUE_CHUNK(cc, buf) do {                                              \
    uint32_t base = sb + (buf) * 4 * GT;                                       \
    const __nv_bfloat16* srcs[4] = {Ah, Al, Bh, Bl};                           \
    _Pragma("unroll")                                                          \
    for (int tile = 0; tile < 4; tile++) {                                     \
      int rb = (tile < 2) ? bm : bn;                                           \
      const __nv_bfloat16* sp = srcs[tile];                                    \
      _Pragma("unroll")                                                        \
      for (int s = 0; s < 4; s++) {                                            \
        const __nv_bfloat16* src = sp + (size_t)(rb + ldrow[s]) * K +          \
                                   (cc) * 64 + ldkcol[s] * 8;                  \
        CP_ASYNC16(base + tile * GT + lddst[s], src);                          \
      }                                                                        \
    }                                                                          \
    CP_COMMIT();                                                               \
  } while (0)

  ISSUE_CHUNK(0, 0);

  for (int c = 0; c < NC; c++) {
    const int buf = c & 1;
    if (c + 1 < NC) { ISSUE_CHUNK(c + 1, buf ^ 1); CP_WAIT1(); }
    else            { CP_WAIT0(); }
    __syncthreads();

    const uint32_t tb = sb + buf * 4 * GT;
#pragma unroll
    for (int kc = 0; kc < 4; kc++) {
      uint32_t ah[4][4], al[4][4], bh[2][4], bl[2][4];
      const uint32_t kA = (uint32_t)((kc * 32 + akb) ^ kxor);
      const uint32_t kB = (uint32_t)((kc * 32 + bkb) ^ kxor);
#pragma unroll
      for (int i = 0; i < 4; i++) {
        ldsm4(ah[i], tb + aoff[i] + kA);
        ldsm4(al[i], tb + GT + aoff[i] + kA);
      }
#pragma unroll
      for (int j = 0; j < 2; j++) {
        ldsm4(bh[j], tb + 2 * GT + boff[j] + kB);
        ldsm4(bl[j], tb + 3 * GT + boff[j] + kB);
      }
#pragma unroll
      for (int i = 0; i < 4; i++)
#pragma unroll
        for (int jf = 0; jf < 4; jf++) {
          const uint32_t* bph = &bh[jf >> 1][(jf & 1) * 2];
          const uint32_t* bpl = &bl[jf >> 1][(jf & 1) * 2];
          mma_bf16(acc[i][jf], ah[i], bph);
          mma_bf16(acc[i][jf], ah[i], bpl);
          mma_bf16(acc[i][jf], al[i], bph);
        }
    }
    __syncthreads();
  }
#undef ISSUE_CHUNK

  const int r0 = bm + wm + (l >> 2);
  const int c0 = bn + wn + (l & 3) * 2;
#pragma unroll
  for (int i = 0; i < 4; i++)
#pragma unroll
    for (int j = 0; j < 4; j++) {
      float* p0 = C + (size_t)(r0 + i * 16) * N + c0 + j * 8;
      float* p1 = C + (size_t)(r0 + i * 16 + 8) * N + c0 + j * 8;
      *(float2*)p0 = make_float2(acc[i][j][0], acc[i][j][1]);
      *(float2*)p1 = make_float2(acc[i][j][2], acc[i][j][3]);
    }
}

// ---------------- RMSNorm + RoPE (+gain) -> bf16 hi/lo planes ------------------
__global__ void rms_rope_split(const float* __restrict__ X, const float* __restrict__ gain,
                               __nv_bfloat16* __restrict__ Hh, __nv_bfloat16* __restrict__ Ll,
                               int nheads, int nrows) {
  int gw = (int)((blockIdx.x * blockDim.x + threadIdx.x) >> 5);
  int lane = threadIdx.x & 31;
  if (gw >= nrows) return;
  int h = gw % nheads;
  int bt = gw / nheads;
  int t = bt % T_;
  const float* row = X + (size_t)bt * (nheads * HD_) + h * HD_;
  float2 x1 = *(const float2*)(row + lane * 2);
  float2 x2 = *(const float2*)(row + 64 + lane * 2);
  float ss = x1.x*x1.x + x1.y*x1.y + x2.x*x2.x + x2.y*x2.y;
#pragma unroll
  for (int o = 16; o > 0; o >>= 1) ss += __shfl_xor_sync(0xffffffffu, ss, o);
  float rn = rsqrtf(ss * (1.f / HD_) + EPS_);
  float gm = (gain != nullptr) ? gain[h] * rn : rn;
  x1.x *= gm; x1.y *= gm; x2.x *= gm; x2.y *= gm;
  float4 cs = *(const float4*)(g_rope + (size_t)t * 128 + lane * 4);
  float o1x = x1.x * cs.x - x2.x * cs.y;
  float o1y = x1.y * cs.z - x2.y * cs.w;
  float o2x = x2.x * cs.x + x1.x * cs.y;
  float o2y = x2.y * cs.z + x1.y * cs.w;
  size_t base = (size_t)bt * (nheads * HD_) + h * HD_;
  // hi/lo split, store pairs
  __nv_bfloat16 h1a = __float2bfloat16(o1x), h1b = __float2bfloat16(o1y);
  __nv_bfloat16 h2a = __float2bfloat16(o2x), h2b = __float2bfloat16(o2y);
  __nv_bfloat162 hp1{h1a, h1b}, hp2{h2a, h2b};
  __nv_bfloat162 lp1{__float2bfloat16(o1x - __bfloat162float(h1a)),
                     __float2bfloat16(o1y - __bfloat162float(h1b))};
  __nv_bfloat162 lp2{__float2bfloat16(o2x - __bfloat162float(h2a)),
                     __float2bfloat16(o2y - __bfloat162float(h2b))};
  *(uint32_t*)(Hh + base + lane * 2)      = *(uint32_t*)&hp1;
  *(uint32_t*)(Hh + base + 64 + lane * 2) = *(uint32_t*)&hp2;
  *(uint32_t*)(Ll + base + lane * 2)      = *(uint32_t*)&lp1;
  *(uint32_t*)(Ll + base + 64 + lane * 2) = *(uint32_t*)&lp2;
}

// ---------------- V transpose + split: [bt][kv*128+d] -> [bkv][d][t] ----------
__global__ __launch_bounds__(256) void vtrans_kernel(const float* __restrict__ V,
                                                     __nv_bfloat16* __restrict__ Vth,
                                                     __nv_bfloat16* __restrict__ Vtl) {
  __shared__ float tile[32][33];
  const int t0 = blockIdx.x * 32, d0 = blockIdx.y * 32;
  const int bkv = blockIdx.z;
  const int b = bkv >> 2, kv = bkv & 3;
  const int tx = threadIdx.x & 31, ty = threadIdx.x >> 5;
#pragma unroll
  for (int i = 0; i < 4; i++) {
    int t = t0 + ty + i * 8;
    tile[ty + i * 8][tx] = V[(size_t)(b * T_ + t) * KVD_ + kv * 128 + d0 + tx];
  }
  __syncthreads();
#pragma unroll
  for (int i = 0; i < 4; i++) {
    int d = d0 + ty + i * 8;
    float v = tile[tx][ty + i * 8];
    __nv_bfloat16 hi = __float2bfloat16(v);
    __nv_bfloat16 lo = __float2bfloat16(v - __bfloat162float(hi));
    size_t idx = ((size_t)bkv * 128 + d) * T_ + t0 + tx;
    Vth[idx] = hi;
    Vtl[idx] = lo;
  }
}

// ---------------- HMMA flash attention -----------------------------------------
// smem: Qh[2ch][128][64] 32KB, Ql 32KB, then 2 buffers of {Kh 16KB, Kl 16KB, Vth 16KB, Vtl 16KB}
#define FQ_OFF   0
#define FBUF_OFF 65536
#define SMEM_FLA (65536 + 2 * 65536)   // 192KB

__global__ __launch_bounds__(256, 1) void flash_hmma(
    const __nv_bfloat16* __restrict__ Qh, const __nv_bfloat16* __restrict__ Ql,
    const __nv_bfloat16* __restrict__ Kh, const __nv_bfloat16* __restrict__ Kl,
    const __nv_bfloat16* __restrict__ Vth, const __nv_bfloat16* __restrict__ Vtl,
    float* __restrict__ Y) {
  extern __shared__ char sm[];
  const uint32_t sb = smem_u32(sm);
  const int tid = threadIdx.x;
  const int l = tid & 31, w = tid >> 5;
  const int qtile = gridDim.x - 1 - blockIdx.x;
  const int bh = blockIdx.y;
  const int b = bh >> 4, h = bh & 15, kv = h >> 2;
  const int q0 = qtile * 128;
  const int wm = w * 16;

  const int arow = (l & 7) + ((l >> 3) & 1) * 8;
  const int akb  = (l >> 4) * 16;
  const int brow = (l & 7) + (l >> 4) * 8;
  const int bkb  = ((l >> 3) & 1) * 16;
  const uint32_t kxA = (uint32_t)((l & 7) << 4);

  // ---- issue Q loads (own commit group) ----
#pragma unroll
  for (int s = 0; s < 8; s++) {
    int ch = tid + s * 256;              // 0..2047
    int kchunk = ch >> 10;
    int cid = ch & 1023;
    int r = cid >> 3, cc = cid & 7;
    uint32_t dst = (uint32_t)(kchunk * 16384 + r * 128 + ((cc * 16) ^ ((r & 7) << 4)));
    size_t src = (size_t)(b * T_ + q0 + r) * DIM_ + h * HD_ + kchunk * 64 + cc * 8;
    CP_ASYNC16(sb + FQ_OFF + dst, Qh + src);
    CP_ASYNC16(sb + FQ_OFF + 32768 + dst, Ql + src);
  }
  CP_COMMIT();

#define FKV_ISSUE(tt, buf) do {                                                 \
    uint32_t base = sb + FBUF_OFF + (buf) * 65536;                              \
    int s0_ = (tt) * 64;                                                        \
    _Pragma("unroll")                                                           \
    for (int s = 0; s < 4; s++) {                                               \
      int ch = tid + s * 256;            /* K: 1024 chunks */                   \
      int kchunk = ch >> 9;                                                     \
      int cid = ch & 511;                                                       \
      int r = cid >> 3, cc = cid & 7;                                           \
      uint32_t dst = (uint32_t)(kchunk * 8192 + r * 128 +                       \
                                ((cc * 16) ^ ((r & 7) << 4)));                  \
      size_t src = (size_t)(b * T_ + s0_ + r) * KVD_ + kv * 128 +               \
                   kchunk * 64 + cc * 8;                                        \
      CP_ASYNC16(base + dst, Kh + src);                                         \
      CP_ASYNC16(base + 16384 + dst, Kl + src);                                 \
    }                                                                           \
    _Pragma("unroll")                                                           \
    for (int s = 0; s < 4; s++) {                                               \
      int ch = tid + s * 256;            /* Vt: 1024 chunks */                  \
      int r = ch >> 3, cc = ch & 7;                                             \
      uint32_t dst = (uint32_t)(r * 128 + ((cc * 16) ^ ((r & 7) << 4)));        \
      size_t src = ((size_t)(b * 4 + kv) * 128 + r) * T_ + s0_ + cc * 8;        \
      CP_ASYNC16(base + 32768 + dst, Vth + src);                                \
      CP_ASYNC16(base + 49152 + dst, Vtl + src);                                \
    }                                                                           \
    CP_COMMIT();                                                                \
  } while (0)

  const int nt = (q0 + 128) / 64;
  FKV_ISSUE(0, 0);

  float ys[16][4];
#pragma unroll
  for (int i = 0; i < 16; i++)
#pragma unroll
    for (int r = 0; r < 4; r++) ys[i][r] = 0.f;
  float m0 = -INFINITY, m1 = -INFINITY, l0 = 0.f, l1 = 0.f;
  const int rg0 = q0 + wm + (l >> 2);       // rows for c0,c1
  const int wrow_max = q0 + wm + 15;

  for (int t = 0; t < nt; t++) {
    const int buf = t & 1;
    if (t + 1 < nt) { FKV_ISSUE(t + 1, buf ^ 1); CP_WAIT1(); }
    else            { CP_WAIT0(); }
    __syncthreads();

    const int s0 = t * 64;
    if (s0 <= wrow_max) {                   // warp-uniform
      const uint32_t KB = sb + FBUF_OFF + buf * 65536;
      const uint32_t VB = KB + 32768;
      float sacc[8][4];
#pragma unroll
      for (int j = 0; j < 8; j++)
#pragma unroll
        for (int r = 0; r < 4; r++) sacc[j][r] = 0.f;

      // S = Qh*Kh^T + Qh*Kl^T + Ql*Kh^T
#pragma unroll
      for (int ks = 0; ks < 8; ks++) {
        const int kchunk = ks >> 2, kc = ks & 3;
        uint32_t ah[4], al[4];
        uint32_t qa = sb + FQ_OFF + kchunk * 16384 + (wm + arow) * 128 +
                      (((kc * 32 + akb)) ^ kxA);
        ldsm4(ah, qa);
        ldsm4(al, qa + 32768);
#pragma unroll
        for (int j = 0; j < 4; j++) {
          uint32_t bh4[4], bl4[4];
          uint32_t ka = KB + kchunk * 8192 + (j * 16 + brow) * 128 +
                        (((kc * 32 + bkb)) ^ kxA);
          ldsm4(bh4, ka);
          ldsm4(bl4, ka + 16384);
          mma_bf16(sacc[2 * j],     ah, &bh4[0]);
          mma_bf16(sacc[2 * j],     ah, &bl4[0]);
          mma_bf16(sacc[2 * j],     al, &bh4[0]);
          mma_bf16(sacc[2 * j + 1], ah, &bh4[2]);
          mma_bf16(sacc[2 * j + 1], ah, &bl4[2]);
          mma_bf16(sacc[2 * j + 1], al, &bh4[2]);
        }
      }

      // mask + scale
#pragma unroll
      for (int j = 0; j < 8; j++) {
        int cg = s0 + j * 8 + (l & 3) * 2;
        sacc[j][0] = (cg     <= rg0)     ? sacc[j][0] * SCALE_ : -INFINITY;
        sacc[j][1] = (cg + 1 <= rg0)     ? sacc[j][1] * SCALE_ : -INFINITY;
        sacc[j][2] = (cg     <= rg0 + 8) ? sacc[j][2] * SCALE_ : -INFINITY;
        sacc[j][3] = (cg + 1 <= rg0 + 8) ? sacc[j][3] * SCALE_ : -INFINITY;
      }
      // row max
      float rm0 = -INFINITY, rm1 = -INFINITY;
#pragma unroll
      for (int j = 0; j < 8; j++) {
        rm0 = fmaxf(rm0, fmaxf(sacc[j][0], sacc[j][1]));
        rm1 = fmaxf(rm1, fmaxf(sacc[j][2], sacc[j][3]));
      }
      rm0 = fmaxf(rm0, __shfl_xor_sync(0xffffffffu, rm0, 1));
      rm0 = fmaxf(rm0, __shfl_xor_sync(0xffffffffu, rm0, 2));
      rm1 = fmaxf(rm1, __shfl_xor_sync(0xffffffffu, rm1, 1));
      rm1 = fmaxf(rm1, __shfl_xor_sync(0xffffffffu, rm1, 2));
      float nm0 = fmaxf(m0, rm0), nm1 = fmaxf(m1, rm1);
      float a0 = expf(m0 - nm0), a1 = expf(m1 - nm1);
      m0 = nm0; m1 = nm1;
      l0 *= a0; l1 *= a1;
#pragma unroll
      for (int i = 0; i < 16; i++) {
        ys[i][0] *= a0; ys[i][1] *= a0; ys[i][2] *= a1; ys[i][3] *= a1;
      }
      // p = exp(s - m)
#pragma unroll
      for (int j = 0; j < 8; j++) {
        sacc[j][0] = expf(sacc[j][0] - nm0);
        sacc[j][1] = expf(sacc[j][1] - nm0);
        sacc[j][2] = expf(sacc[j][2] - nm1);
        sacc[j][3] = expf(sacc[j][3] - nm1);
        l0 += sacc[j][0] + sacc[j][1];
        l1 += sacc[j][2] + sacc[j][3];
      }

      // Y += Ph*Vth^T + Ph*Vtl^T + Pl*Vth^T
#pragma unroll
      for (int u = 0; u < 4; u++) {
        uint32_t pha[4], pla[4];
        {
          float p00 = sacc[2*u][0], p01 = sacc[2*u][1];
          float p02 = sacc[2*u][2], p03 = sacc[2*u][3];
          float p10 = sacc[2*u+1][0], p11 = sacc[2*u+1][1];
          float p12 = sacc[2*u+1][2], p13 = sacc[2*u+1][3];
          pha[0] = pack_bf2(p00, p01); pha[1] = pack_bf2(p02, p03);
          pha[2] = pack_bf2(p10, p11); pha[3] = pack_bf2(p12, p13);
          __nv_bfloat162 h0 = *(__nv_bfloat162*)&pha[0];
          __nv_bfloat162 h1 = *(__nv_bfloat162*)&pha[1];
          __nv_bfloat162 h2 = *(__nv_bfloat162*)&pha[2];
          __nv_bfloat162 h3 = *(__nv_bfloat162*)&pha[3];
          pla[0] = pack_bf2(p00 - __bfloat162float(h0.x), p01 - __bfloat162float(h0.y));
          pla[1] = pack_bf2(p02 - __bfloat162float(h1.x), p03 - __bfloat162float(h1.y));
          pla[2] = pack_bf2(p10 - __bfloat162float(h2.x), p11 - __bfloat162float(h2.y));
          pla[3] = pack_bf2(p12 - __bfloat162float(h3.x), p13 - __bfloat162float(h3.y));
        }
#pragma unroll
        for (int jj = 0; jj < 8; jj++) {
          uint32_t vh4[4], vl4[4];
          uint32_t va = VB + (jj * 16 + brow) * 128 + (((u * 32 + bkb)) ^ kxA);
          ldsm4(vh4, va);
          ldsm4(vl4, va + 16384);
          mma_bf16(ys[2 * jj],     pha, &vh4[0]);
          mma_bf16(ys[2 * jj],     pha, &vl4[0]);
          mma_bf16(ys[2 * jj],     pla, &vh4[0]);
          mma_bf16(ys[2 * jj + 1], pha, &vh4[2]);
          mma_bf16(ys[2 * jj + 1], pha, &vl4[2]);
          mma_bf16(ys[2 * jj + 1], pla, &vh4[2]);
        }
      }
    }
    __syncthreads();
  }
#undef FKV_ISSUE

  // reduce l across quad, write out
  l0 += __shfl_xor_sync(0xffffffffu, l0, 1);
  l0 += __shfl_xor_sync(0xffffffffu, l0, 2);
  l1 += __shfl_xor_sync(0xffffffffu, l1, 1);
  l1 += __shfl_xor_sync(0xffffffffu, l1, 2);
  float i0 = 1.f / l0, i1 = 1.f / l1;
#pragma unroll
  for (int tt = 0; tt < 16; tt++) {
    int col = h * HD_ + tt * 8 + (l & 3) * 2;
    float* p0 = Y + (size_t)(b * T_ + rg0) * DIM_ + col;
    float* p1 = Y + (size_t)(b * T_ + rg0 + 8) * DIM_ + col;
    *(float2*)p0 = make_float2(ys[tt][0] * i0, ys[tt][1] * i0);
    *(float2*)p1 = make_float2(ys[tt][2] * i1, ys[tt][3] * i1);
  }
}

// ---------------- v-direction rejection ----------------------------------------
__global__ __launch_bounds__(256) void vproj_kernel(const float* __restrict__ V,
                                                    float* __restrict__ Y) {
  const int gw = (blockIdx.x * blockDim.x + threadIdx.x) >> 5;
  const int lane = threadIdx.x & 31;
  if (gw >= B_ * T_ * NKV_) return;
  const int bt = gw >> 2, kv = gw & 3;
  float4 v4 = *(const float4*)(V + (size_t)bt * KVD_ + kv * HD_ + lane * 4);
  float ss = v4.x*v4.x + v4.y*v4.y + v4.z*v4.z + v4.w*v4.w;
#pragma unroll
  for (int o = 16; o > 0; o >>= 1) ss += __shfl_xor_sync(0xffffffffu, ss, o);
  float inv = 1.f / (sqrtf(ss) + 1e-8f);
  float4 vn = make_float4(v4.x*inv, v4.y*inv, v4.z*inv, v4.w*inv);
#pragma unroll
  for (int g = 0; g < 4; g++) {
    float* yp = Y + (size_t)bt * DIM_ + (kv * 4 + g) * HD_ + lane * 4;
    float4 y4 = *(float4*)yp;
    float p = y4.x*vn.x + y4.y*vn.y + y4.z*vn.z + y4.w*vn.w;
#pragma unroll
    for (int o = 16; o > 0; o >>= 1) p += __shfl_xor_sync(0xffffffffu, p, o);
    y4.x -= p * vn.x; y4.y -= p * vn.y; y4.z -= p * vn.z; y4.w -= p * vn.w;
    *(float4*)yp = y4;
  }
}

// ---------------- launch ------------------------------------------------------
extern "C" void kernel_launch(void* const* d_in, const int* in_sizes, int n_in,
                              void* d_out, int out_size) {
  const float* x     = (const float*)d_in[0];
  const float* Wq    = (const float*)d_in[1];
  const float* Wk    = (const float*)d_in[2];
  const float* Wv    = (const float*)d_in[3];
  const float* Wproj = (const float*)d_in[4];
  const float* qgain = (const float*)d_in[5];
  float* out = (float*)d_out;

  float *qb, *kb, *vb, *yb;
  cudaGetSymbolAddress((void**)&qb, g_q);
  cudaGetSymbolAddress((void**)&kb, g_k);
  cudaGetSymbolAddress((void**)&vb, g_v);
  cudaGetSymbolAddress((void**)&yb, g_y);
  __nv_bfloat16 *xh, *xl, *wqh, *wql, *wkh, *wkl, *wvh, *wvl, *wph, *wpl;
  __nv_bfloat16 *qh, *ql, *kh, *kl, *vth, *vtl;
  cudaGetSymbolAddress((void**)&xh, g_xh);
  cudaGetSymbolAddress((void**)&xl, g_xl);
  cudaGetSymbolAddress((void**)&wqh, g_wqh);
  cudaGetSymbolAddress((void**)&wql, g_wql);
  cudaGetSymbolAddress((void**)&wkh, g_wkh);
  cudaGetSymbolAddress((void**)&wkl, g_wkl);
  cudaGetSymbolAddress((void**)&wvh, g_wvh);
  cudaGetSymbolAddress((void**)&wvl, g_wvl);
  cudaGetSymbolAddress((void**)&wph, g_wph);
  cudaGetSymbolAddress((void**)&wpl, g_wpl);
  cudaGetSymbolAddress((void**)&qh, g_qh);
  cudaGetSymbolAddress((void**)&ql, g_ql);
  cudaGetSymbolAddress((void**)&kh, g_kh);
  cudaGetSymbolAddress((void**)&kl, g_kl);
  cudaGetSymbolAddress((void**)&vth, g_vth);
  cudaGetSymbolAddress((void**)&vtl, g_vtl);

  cudaFuncSetAttribute(gemm_hmma, cudaFuncAttributeMaxDynamicSharedMemorySize, SMEM_HG);
  cudaFuncSetAttribute(flash_hmma, cudaFuncAttributeMaxDynamicSharedMemorySize, SMEM_FLA);

  const int M = B_ * T_;
  dim3 gbig(DIM_ / 128, M / 128);
  dim3 gkv(KVD_ / 128, M / 128);

  rope_table_kernel<<<(T_ * 64 + 255) / 256, 256>>>();

  split_kernel<<<(M * DIM_ / 4 + 255) / 256, 256>>>(x, xh, xl, M * DIM_ / 4);
  split_kernel<<<(DIM_ * DIM_ / 4 + 255) / 256, 256>>>(Wq, wqh, wql, DIM_ * DIM_ / 4);
  split_kernel<<<(KVD_ * DIM_ / 4 + 255) / 256, 256>>>(Wk, wkh, wkl, KVD_ * DIM_ / 4);
  split_kernel<<<(KVD_ * DIM_ / 4 + 255) / 256, 256>>>(Wv, wvh, wvl, KVD_ * DIM_ / 4);
  split_kernel<<<(DIM_ * DIM_ / 4 + 255) / 256, 256>>>(Wproj, wph, wpl, DIM_ * DIM_ / 4);

  gemm_hmma<<<gbig, 256, SMEM_HG>>>(xh, xl, wqh, wql, qb, DIM_, DIM_);
  gemm_hmma<<<gkv, 256, SMEM_HG>>>(xh, xl, wkh, wkl, kb, KVD_, DIM_);
  gemm_hmma<<<gkv, 256, SMEM_HG>>>(xh, xl, wvh, wvl, vb, KVD_, DIM_);

  int qrows = M * H_;
  int krows = M * NKV_;
  rms_rope_split<<<(qrows * 32 + 255) / 256, 256>>>(qb, qgain, qh, ql, H_, qrows);
  rms_rope_split<<<(krows * 32 + 255) / 256, 256>>>(kb, nullptr, kh, kl, NKV_, krows);

  dim3 gvt(T_ / 32, HD_ / 32, B_ * NKV_);
  vtrans_kernel<<<gvt, 256>>>(vb, vth, vtl);

  dim3 gf(T_ / 128, B_ * H_);
  flash_hmma<<<gf, 256, SMEM_FLA>>>(qh, ql, kh, kl, vth, vtl, yb);

  vproj_kernel<<<(M * NKV_ * 32 + 255) / 256, 256>>>(vb, yb);

  split_kernel<<<(M * DIM_ / 4 + 255) / 256, 256>>>(yb, xh, xl, M * DIM_ / 4);
  gemm_hmma<<<gbig, 256, SMEM_HG>>>(xh, xl, wph, wpl, out, DIM_, DIM_);
}